// round 1
// baseline (speedup 1.0000x reference)
#include <cuda_runtime.h>
#include <cuda_bf16.h>
#include <cstdint>

// Problem constants (fixed by the dataset)
#define NNODES 100000
#define INC    128
#define OUTC   128

// Scratch: device globals (no allocation allowed)
__device__ float g_sum[(size_t)NNODES * INC];   // segment sums, then normalized agg
__device__ float g_deg[NNODES];                 // degree counts (float)

// ---------------------------------------------------------------------------
// Kernel 1: zero the scratch buffers
// ---------------------------------------------------------------------------
__global__ void zero_scratch() {
    int idx = blockIdx.x * blockDim.x + threadIdx.x;
    int total = NNODES * INC;
    if (idx < total)        g_sum[idx] = 0.0f;
    else if (idx < total + NNODES) g_deg[idx - total] = 0.0f;
}

// ---------------------------------------------------------------------------
// Kernel 2: edge scatter. One warp per edge; each lane reduces one float4
// (128 floats per row = 32 float4). red.global.add.v4.f32 (sm_90+).
// ---------------------------------------------------------------------------
__global__ void edge_scatter(const float* __restrict__ x,
                             const int* __restrict__ edge_row,
                             const int* __restrict__ edge_col,
                             int E) {
    int tid  = blockIdx.x * blockDim.x + threadIdx.x;
    int e    = tid >> 5;
    int lane = tid & 31;
    if (e >= E) return;

    int dst = edge_row[e];
    int src = edge_col[e];

    const float4* xs = reinterpret_cast<const float4*>(x + (size_t)src * INC);
    float4 v = xs[lane];

    float4* d = reinterpret_cast<float4*>(g_sum + (size_t)dst * INC) + lane;
    asm volatile("red.global.add.v4.f32 [%0], {%1, %2, %3, %4};"
                 :: "l"(d), "f"(v.x), "f"(v.y), "f"(v.z), "f"(v.w)
                 : "memory");

    if (lane == 0) atomicAdd(&g_deg[dst], 1.0f);
}

// ---------------------------------------------------------------------------
// Kernel 3: normalize sums -> mean aggregation (in place)
// ---------------------------------------------------------------------------
__global__ void normalize_mean() {
    int idx = blockIdx.x * blockDim.x + threadIdx.x;
    if (idx >= NNODES * INC) return;
    int row = idx >> 7;  // /128
    float d = fmaxf(g_deg[row], 1.0f);
    g_sum[idx] = g_sum[idx] / d;
}

// ---------------------------------------------------------------------------
// Kernel 4: fused GEMM:  out = relu( [agg | x] @ [W_l ; W_r] + b_l )
//   A: 100000 x 256 (virtual: k<128 -> g_sum(agg), k>=128 -> x)
//   B: 256 x 128    (virtual: k<128 -> W_l[k],    k>=128 -> W_r[k-128])
// Tile: 128 rows x 128 cols per block, 256 threads, 8x8 micro-tile/thread,
// K chunked by 16 through shared memory.
// ---------------------------------------------------------------------------
#define KC 16
__global__ __launch_bounds__(256, 2)
void fused_gemm(const float* __restrict__ x,
                const float* __restrict__ Wl,
                const float* __restrict__ bl,
                const float* __restrict__ Wr,
                float* __restrict__ out,
                int Nn) {
    __shared__ float As[128 * KC];   // [row][kk]
    __shared__ float Bs[KC * 128];   // [kk][col]

    int t  = threadIdx.x;
    int tx = t & 15;        // 0..15  -> col group
    int ty = t >> 4;        // 0..15  -> row group
    int row_base = blockIdx.x * 128;

    float acc[8][8];
#pragma unroll
    for (int i = 0; i < 8; i++)
#pragma unroll
        for (int j = 0; j < 8; j++) acc[i][j] = 0.0f;

    for (int chunk = 0; chunk < 256 / KC; chunk++) {
        int k0 = chunk * KC;

        // Load A tile: 128 rows x KC. element e: kk = e&15, row = e>>4
#pragma unroll
        for (int i = 0; i < (128 * KC) / 256; i++) {
            int e   = t + 256 * i;
            int kk  = e & (KC - 1);
            int row = e >> 4;
            int rg  = row_base + row;
            int kg  = k0 + kk;
            float v = 0.0f;
            if (rg < Nn) {
                if (kg < 128) v = g_sum[(size_t)rg * INC + kg];
                else          v = x[(size_t)rg * INC + (kg - 128)];
            }
            As[row * KC + kk] = v;
        }
        // Load B tile: KC x 128. element e: col = e&127, kk = e>>7
#pragma unroll
        for (int i = 0; i < (KC * 128) / 256; i++) {
            int e   = t + 256 * i;
            int col = e & 127;
            int kk  = e >> 7;
            int kg  = k0 + kk;
            float v;
            if (kg < 128) v = Wl[kg * OUTC + col];
            else          v = Wr[(kg - 128) * OUTC + col];
            Bs[kk * 128 + col] = v;
        }
        __syncthreads();

#pragma unroll
        for (int kk = 0; kk < KC; kk++) {
            float a[8], b[8];
#pragma unroll
            for (int i = 0; i < 8; i++) a[i] = As[(ty + 16 * i) * KC + kk];
#pragma unroll
            for (int j = 0; j < 8; j++) b[j] = Bs[kk * 128 + tx + 16 * j];
#pragma unroll
            for (int i = 0; i < 8; i++)
#pragma unroll
                for (int j = 0; j < 8; j++)
                    acc[i][j] = fmaf(a[i], b[j], acc[i][j]);
        }
        __syncthreads();
    }

    // Epilogue: bias + relu + store
    float bias[8];
#pragma unroll
    for (int j = 0; j < 8; j++) bias[j] = bl[tx + 16 * j];

#pragma unroll
    for (int i = 0; i < 8; i++) {
        int r = row_base + ty + 16 * i;
        if (r < Nn) {
#pragma unroll
            for (int j = 0; j < 8; j++) {
                out[(size_t)r * OUTC + tx + 16 * j] =
                    fmaxf(acc[i][j] + bias[j], 0.0f);
            }
        }
    }
}

// ---------------------------------------------------------------------------
// Launch
// ---------------------------------------------------------------------------
extern "C" void kernel_launch(void* const* d_in, const int* in_sizes, int n_in,
                              void* d_out, int out_size) {
    const float* x        = (const float*)d_in[0];
    const int*   edge_row = (const int*)d_in[1];
    const int*   edge_col = (const int*)d_in[2];
    const float* Wl       = (const float*)d_in[3];
    const float* bl       = (const float*)d_in[4];
    const float* Wr       = (const float*)d_in[5];
    float*       out      = (float*)d_out;

    int E = in_sizes[1];

    // 1) zero scratch
    {
        int total = NNODES * INC + NNODES;
        zero_scratch<<<(total + 255) / 256, 256>>>();
    }
    // 2) edge scatter (one warp per edge)
    {
        long long threads = (long long)E * 32;
        int blocks = (int)((threads + 255) / 256);
        edge_scatter<<<blocks, 256>>>(x, edge_row, edge_col, E);
    }
    // 3) mean normalize
    {
        int total = NNODES * INC;
        normalize_mean<<<(total + 255) / 256, 256>>>();
    }
    // 4) fused dual GEMM + bias + relu
    {
        int blocks = (NNODES + 127) / 128;
        fused_gemm<<<blocks, 256>>>(x, Wl, bl, Wr, out, NNODES);
    }
}

// round 3
// speedup vs baseline: 1.3228x; 1.3228x over previous
#include <cuda_runtime.h>
#include <cuda_bf16.h>
#include <cstdint>

// Problem constants (fixed by the dataset)
#define NNODES 100000
#define INC    128
#define OUTC   128

typedef unsigned long long ull;

// Scratch: device globals (no allocation allowed)
__device__ float g_sum[(size_t)NNODES * INC];   // segment sums (un-normalized)
__device__ float g_deg[NNODES];                 // degree counts (float)

// Packed dual-fp32 FMA (Blackwell f32x2 path; 2x fp32 FMA throughput)
#define FMA_F32X2(d, a, b) \
    asm("fma.rn.f32x2 %0, %1, %2, %0;" : "+l"(d) : "l"(a), "l"(b))

// ---------------------------------------------------------------------------
// Kernel 1: zero the scratch buffers
// ---------------------------------------------------------------------------
__global__ void zero_scratch() {
    int idx = blockIdx.x * blockDim.x + threadIdx.x;
    int total = NNODES * INC;
    if (idx < total)                  g_sum[idx] = 0.0f;
    else if (idx < total + NNODES)    g_deg[idx - total] = 0.0f;
}

// ---------------------------------------------------------------------------
// Kernel 2: edge scatter. One warp per edge; each lane reduces one float4.
// ---------------------------------------------------------------------------
__global__ void edge_scatter(const float* __restrict__ x,
                             const int* __restrict__ edge_row,
                             const int* __restrict__ edge_col,
                             int E) {
    int tid  = blockIdx.x * blockDim.x + threadIdx.x;
    int e    = tid >> 5;
    int lane = tid & 31;
    if (e >= E) return;

    int dst = edge_row[e];
    int src = edge_col[e];

    const float4* xs = reinterpret_cast<const float4*>(x + (size_t)src * INC);
    float4 v = xs[lane];

    float4* d = reinterpret_cast<float4*>(g_sum + (size_t)dst * INC) + lane;
    asm volatile("red.global.add.v4.f32 [%0], {%1, %2, %3, %4};"
                 :: "l"(d), "f"(v.x), "f"(v.y), "f"(v.z), "f"(v.w)
                 : "memory");

    if (lane == 0) atomicAdd(&g_deg[dst], 1.0f);
}

// ---------------------------------------------------------------------------
// Kernel 3: fused GEMM:  out = relu( [agg | x] @ [W_l ; W_r] + b_l )
//   A: 100000 x 256 virtual (k<128 -> g_sum * 1/deg fused, k>=128 -> x)
//   B: 256 x 128 virtual    (k<128 -> W_l[k],              k>=128 -> W_r[k-128])
// Tile 128x128 per block, 256 threads, 8x8 micro-tile per thread with
// f32x2 packed FMA (acc = 8 rows x 4 f32x2 column-pairs).
// A stored in SMEM pre-duplicated (a,a) so inner loop is LDS.64 + FFMA2 only.
// ---------------------------------------------------------------------------
#define KC 32
#define ASTRIDE 33  // float2 units, padded (33*8B = 264B -> bank offset 2)

__global__ __launch_bounds__(256, 2)
void fused_gemm(const float* __restrict__ x,
                const float* __restrict__ Wl,
                const float* __restrict__ bl,
                const float* __restrict__ Wr,
                float* __restrict__ out,
                int Nn) {
    __shared__ float2 As2[128 * ASTRIDE];   // [row][kk] duplicated (a,a)
    __shared__ float  Bs[KC * 128];         // [kk][col]
    __shared__ float  rdeg[128];

    int t  = threadIdx.x;
    int tx = t & 15;        // 0..15 -> column pair group (cols tx*2+32j, +1)
    int ty = t >> 4;        // 0..15 -> row group (rows ty+16i)
    int row_base = blockIdx.x * 128;

    // Per-row 1/deg (mean normalization fused into A load)
    if (t < 128) {
        int r = row_base + t;
        rdeg[t] = (r < Nn) ? (1.0f / fmaxf(g_deg[r], 1.0f)) : 0.0f;
    }
    __syncthreads();

    ull acc[8][4];
#pragma unroll
    for (int i = 0; i < 8; i++)
#pragma unroll
        for (int j = 0; j < 4; j++) acc[i][j] = 0ull;

    for (int chunk = 0; chunk < 256 / KC; chunk++) {
        int k0 = chunk * KC;

        // ---- Load A tile: 128 rows x KC floats = 1024 float4, 4 per thread
#pragma unroll
        for (int i = 0; i < 4; i++) {
            int idx = t + 256 * i;        // float4 index
            int row = idx >> 3;           // 8 float4 per row (KC=32)
            int f4  = idx & 7;
            int rg  = row_base + row;
            float4 v = make_float4(0.f, 0.f, 0.f, 0.f);
            if (rg < Nn) {
                if (k0 < 128) {
                    v = *reinterpret_cast<const float4*>(
                        g_sum + (size_t)rg * INC + k0 + f4 * 4);
                    float s = rdeg[row];
                    v.x *= s; v.y *= s; v.z *= s; v.w *= s;
                } else {
                    v = *reinterpret_cast<const float4*>(
                        x + (size_t)rg * INC + (k0 - 128) + f4 * 4);
                }
            }
            float2* dst = &As2[row * ASTRIDE + f4 * 4];
            dst[0] = make_float2(v.x, v.x);
            dst[1] = make_float2(v.y, v.y);
            dst[2] = make_float2(v.z, v.z);
            dst[3] = make_float2(v.w, v.w);
        }

        // ---- Load B tile: KC x 128 floats = 1024 float4, 4 per thread
#pragma unroll
        for (int i = 0; i < 4; i++) {
            int idx  = t + 256 * i;       // float4 index
            int kk   = idx >> 5;          // 32 float4 per k-row
            int c4   = idx & 31;
            int kg   = k0 + kk;
            float4 v;
            if (kg < 128) v = *reinterpret_cast<const float4*>(Wl + kg * OUTC + c4 * 4);
            else          v = *reinterpret_cast<const float4*>(Wr + (kg - 128) * OUTC + c4 * 4);
            *reinterpret_cast<float4*>(&Bs[kk * 128 + c4 * 4]) = v;
        }
        __syncthreads();

        // ---- Compute: per kk, 8 LDS.64(a-dup) + 4 LDS.64(b-pair) + 32 FFMA2
#pragma unroll 4
        for (int kk = 0; kk < KC; kk++) {
            ull a2[8], b2[4];
#pragma unroll
            for (int i = 0; i < 8; i++)
                a2[i] = *reinterpret_cast<const ull*>(&As2[(ty + 16 * i) * ASTRIDE + kk]);
#pragma unroll
            for (int j = 0; j < 4; j++)
                b2[j] = *reinterpret_cast<const ull*>(&Bs[kk * 128 + tx * 2 + 32 * j]);
#pragma unroll
            for (int i = 0; i < 8; i++)
#pragma unroll
                for (int j = 0; j < 4; j++)
                    FMA_F32X2(acc[i][j], a2[i], b2[j]);
        }
        __syncthreads();
    }

    // ---- Epilogue: bias + relu + store (float2 per accumulator)
    float2 bias[4];
#pragma unroll
    for (int j = 0; j < 4; j++)
        bias[j] = *reinterpret_cast<const float2*>(bl + tx * 2 + 32 * j);

#pragma unroll
    for (int i = 0; i < 8; i++) {
        int r = row_base + ty + 16 * i;
        if (r < Nn) {
#pragma unroll
            for (int j = 0; j < 4; j++) {
                float2 v = *reinterpret_cast<float2*>(&acc[i][j]);
                float2 o;
                o.x = fmaxf(v.x + bias[j].x, 0.0f);
                o.y = fmaxf(v.y + bias[j].y, 0.0f);
                *reinterpret_cast<float2*>(out + (size_t)r * OUTC + tx * 2 + 32 * j) = o;
            }
        }
    }
}

// ---------------------------------------------------------------------------
// Launch
// ---------------------------------------------------------------------------
extern "C" void kernel_launch(void* const* d_in, const int* in_sizes, int n_in,
                              void* d_out, int out_size) {
    const float* x        = (const float*)d_in[0];
    const int*   edge_row = (const int*)d_in[1];
    const int*   edge_col = (const int*)d_in[2];
    const float* Wl       = (const float*)d_in[3];
    const float* bl       = (const float*)d_in[4];
    const float* Wr       = (const float*)d_in[5];
    float*       out      = (float*)d_out;

    int E = in_sizes[1];

    // 1) zero scratch
    {
        int total = NNODES * INC + NNODES;
        zero_scratch<<<(total + 255) / 256, 256>>>();
    }
    // 2) edge scatter (one warp per edge)
    {
        long long threads = (long long)E * 32;
        int blocks = (int)((threads + 255) / 256);
        edge_scatter<<<blocks, 256>>>(x, edge_row, edge_col, E);
    }
    // 3) fused dual GEMM + mean-normalize + bias + relu
    {
        int blocks = (NNODES + 127) / 128;
        fused_gemm<<<blocks, 256>>>(x, Wl, bl, Wr, out, NNODES);
    }
}